// round 7
// baseline (speedup 1.0000x reference)
#include <cuda_runtime.h>
#include <cuda_fp16.h>

#define NB   8
#define TOUT 256
#define TIN  512
#define LH   128
#define G4   512
#define DIN  128
#define DATT 128

#define OUT_X_ELEMS (NB*TOUT*(LH+DATT))
#define OUT_H_OFF   (OUT_X_ELEMS)
#define OUT_C_OFF   (OUT_X_ELEMS + NB*LH)

// ---- LSTM config ----
#define KREG 80
#define KSM  (LH - KREG)                 // 48
#define WSTRIDE 52
#define LSTM_DSMEM (512 * WSTRIDE * 4)   // 106496 B

// ---- score config ----
#define KPW  68                          // key row stride in half2 words
#define KP4  17                          // ... in uint4
#define S_KEYS_SZ (128 * KPW * 4)        // 34816
#define S_Q_SZ    (8 * 64 * 4)           // 2048
#define S_W3_SZ   (128 * 4)              // 512
#define SCORE_DSMEM (S_KEYS_SZ + S_Q_SZ + S_W3_SZ)   // 37376

__device__ float  g_xz[NB*TOUT*G4];
__device__ __half g_keys_h[NB*TIN*LH];
__device__ __half g_q_h[NB*TOUT*LH];
__device__ float  g_sc[NB*TOUT*TIN];

// ---- fast-MUFU transcendentals (EX2/RCP are the HW-fast ops; tanh.approx is NOT) ----
__device__ __forceinline__ float ex2f(float x) {
    float y; asm("ex2.approx.f32 %0, %1;" : "=f"(y) : "f"(x)); return y;
}
__device__ __forceinline__ float rcpf(float x) {
    float y; asm("rcp.approx.f32 %0, %1;" : "=f"(y) : "f"(x)); return y;
}
__device__ __forceinline__ float tanh_fast(float x) {
    // 1 - 2/(1+e^{2x}); x->+inf: ex2->inf, rcp->0, ->1. x->-inf: ->-1. Stable.
    float t = ex2f(x * 2.885390082f);          // e^{2x}
    return fmaf(-2.0f, rcpf(1.0f + t), 1.0f);
}
__device__ __forceinline__ float sigm_fast(float x) {
    float t = ex2f(x * -1.442695041f);         // e^{-x}
    return rcpf(1.0f + t);
}
__device__ __forceinline__ __half2 u2h2(unsigned u) {
    __half2 h; *reinterpret_cast<unsigned*>(&h) = u; return h;
}

// ---------------------------------------------------------------------------
// K1: fused projections, tiled (unchanged).
// ---------------------------------------------------------------------------
__global__ void __launch_bounds__(128) proj_kernel(
    const float* __restrict__ att, const float* __restrict__ W1,
    const float* __restrict__ b1,  __half* __restrict__ keys_h,
    const float* __restrict__ inp, const float* __restrict__ Wk,
    const float* __restrict__ lbias, float* __restrict__ xz)
{
    int bid = blockIdx.x;
    int j = threadIdx.x;
    if (bid < 256) {
        __shared__ float a_s[16][DATT];
        int row0 = bid * 16;
        for (int i = j; i < 16 * DATT; i += 128) {
            int r = i >> 7, d = i & 127;
            a_s[r][d] = att[(row0 + r) * DATT + d];
        }
        __syncthreads();
        float acc[16];
        float bj = b1[j];
        #pragma unroll
        for (int r = 0; r < 16; r++) acc[r] = bj;
        for (int l = 0; l < DATT; l++) {
            float wl = W1[l * LH + j];
            #pragma unroll
            for (int r = 0; r < 16; r++)
                acc[r] += a_s[r][l] * wl;
        }
        #pragma unroll
        for (int r = 0; r < 16; r++)
            keys_h[(row0 + r) * LH + j] = __float2half(acc[r]);
    } else {
        __shared__ float a_s[8][DIN];
        int row0 = (bid - 256) * 8;
        for (int i = j; i < 8 * DIN; i += 128) {
            int r = i >> 7, d = i & 127;
            a_s[r][d] = inp[(row0 + r) * DIN + d];
        }
        __syncthreads();
        float acc[4][8];
        #pragma unroll
        for (int c = 0; c < 4; c++) {
            float bc = lbias[j + c * 128];
            #pragma unroll
            for (int r = 0; r < 8; r++) acc[c][r] = bc;
        }
        for (int d = 0; d < DIN; d++) {
            float w0 = Wk[d * G4 + j];
            float w1 = Wk[d * G4 + j + 128];
            float w2 = Wk[d * G4 + j + 256];
            float w3 = Wk[d * G4 + j + 384];
            #pragma unroll
            for (int r = 0; r < 8; r++) {
                float av = a_s[r][d];
                acc[0][r] += av * w0;
                acc[1][r] += av * w1;
                acc[2][r] += av * w2;
                acc[3][r] += av * w3;
            }
        }
        #pragma unroll
        for (int r = 0; r < 8; r++) {
            float* o = xz + (row0 + r) * G4;
            o[j] = acc[0][r]; o[j + 128] = acc[1][r];
            o[j + 256] = acc[2][r]; o[j + 384] = acc[3][r];
        }
    }
}

// ---------------------------------------------------------------------------
// K2: LSTM scan — fast-MUFU gates (ex2/rcp), structure unchanged.
// ---------------------------------------------------------------------------
__global__ void __launch_bounds__(512, 1) lstm_kernel(
    const float* __restrict__ xz, const float* __restrict__ Wr,
    float* __restrict__ out)
{
    int b = blockIdx.x;
    int j = threadIdx.x;
    __shared__ float h_s[LH];
    __shared__ float z_s[G4];
    extern __shared__ float w_sT[];

    #pragma unroll 4
    for (int kk = 0; kk < KSM; kk++)
        w_sT[j * WSTRIDE + kk] = Wr[(KREG + kk) * G4 + j];

    float wr[KREG];
    #pragma unroll
    for (int k = 0; k < KREG; k++)
        wr[k] = Wr[k * G4 + j];

    if (j < LH) h_s[j] = 0.0f;
    float c = 0.0f;
    __syncthreads();

    const float* xzb = xz + b * TOUT * G4;
    float xnext = xzb[j];
    bool is_g = (j >= 2 * LH) && (j < 3 * LH);

    for (int t = 0; t < TOUT; t++) {
        float acc0 = xnext;
        float acc1 = 0.0f;
        if (t + 1 < TOUT) xnext = xzb[(t + 1) * G4 + j];

        #pragma unroll
        for (int kk = 0; kk < KREG / 4; kk++) {
            float4 h4 = *reinterpret_cast<const float4*>(&h_s[kk * 4]);
            acc0 += h4.x * wr[kk * 4 + 0];
            acc1 += h4.y * wr[kk * 4 + 1];
            acc0 += h4.z * wr[kk * 4 + 2];
            acc1 += h4.w * wr[kk * 4 + 3];
        }
        #pragma unroll
        for (int kk = 0; kk < KSM / 4; kk++) {
            float4 h4 = *reinterpret_cast<const float4*>(&h_s[KREG + kk * 4]);
            float4 w4 = *reinterpret_cast<const float4*>(&w_sT[j * WSTRIDE + kk * 4]);
            acc0 += h4.x * w4.x;
            acc1 += h4.y * w4.y;
            acc0 += h4.z * w4.z;
            acc1 += h4.w * w4.w;
        }
        float z = acc0 + acc1;
        z_s[j] = is_g ? tanh_fast(z) : sigm_fast(z);
        __syncthreads();
        if (j < LH) {
            c = z_s[LH + j] * c + z_s[j] * z_s[2 * LH + j];
            float h = z_s[3 * LH + j] * tanh_fast(c);
            h_s[j] = h;
            out[(b * TOUT + t) * (LH + DATT) + j] = h;
        }
        __syncthreads();
    }
    if (j < LH) {
        out[OUT_H_OFF + b * LH + j] = h_s[j];
        out[OUT_C_OFF + b * LH + j] = c;
    }
}

// ---------------------------------------------------------------------------
// K3: q = x @ W2 + b2 -> half (unchanged).
// ---------------------------------------------------------------------------
__global__ void __launch_bounds__(128) q_kernel(
    const float* __restrict__ out, const float* __restrict__ W2,
    const float* __restrict__ b2, __half* __restrict__ q_h)
{
    int row0 = blockIdx.x * 16;
    int j = threadIdx.x;
    __shared__ float x_s[16][LH];
    for (int i = j; i < 16 * LH; i += 128) {
        int r = i >> 7, l = i & 127;
        x_s[r][l] = out[(row0 + r) * (LH + DATT) + l];
    }
    __syncthreads();
    float acc[16];
    float bj = b2[j];
    #pragma unroll
    for (int r = 0; r < 16; r++) acc[r] = bj;
    for (int l = 0; l < LH; l++) {
        float wl = W2[l * LH + j];
        #pragma unroll
        for (int r = 0; r < 16; r++)
            acc[r] += x_s[r][l] * wl;
    }
    #pragma unroll
    for (int r = 0; r < 16; r++)
        q_h[(row0 + r) * LH + j] = __float2half(acc[r]);
}

// ---------------------------------------------------------------------------
// K4: raw scores — f32 compute via fast EX2+RCP (no tanh.approx).
//     1024 CTAs x 256 thr, 4 key chains/thread, keys/q staged as half2.
// ---------------------------------------------------------------------------
#define SCORE2(kc, qc, w0, w1, acc) {                                      \
    float2 _z = __half22float2(__hadd2(u2h2(kc), u2h2(qc)));               \
    float _tA = ex2f(_z.x * 2.885390082f);                                 \
    float _tB = ex2f(_z.y * 2.885390082f);                                 \
    float _rA = rcpf(1.0f + _tA);                                          \
    float _rB = rcpf(1.0f + _tB);                                          \
    acc = fmaf(w0, fmaf(-2.0f, _rA, 1.0f), acc);                           \
    acc = fmaf(w1, fmaf(-2.0f, _rB, 1.0f), acc); }

__global__ void __launch_bounds__(256) score_kernel(
    const __half* __restrict__ keys_h_g, const __half* __restrict__ q_h_g,
    const float* __restrict__ W3, float* __restrict__ sc_g)
{
    extern __shared__ char sm[];
    uint4*    keyv = reinterpret_cast<uint4*>(sm);                  // [128][KP4]
    unsigned* qw   = reinterpret_cast<unsigned*>(sm + S_KEYS_SZ);   // [8][64]
    float*    w3f  = reinterpret_cast<float*>(sm + S_KEYS_SZ + S_Q_SZ); // [128]

    int b  = blockIdx.z;
    int q0 = blockIdx.y * 8;
    int k0 = blockIdx.x * 128;
    int tid = threadIdx.x;

    const uint4* kg = reinterpret_cast<const uint4*>(keys_h_g + (b * TIN + k0) * LH);
    for (int i = tid; i < 128 * 16; i += 256) {
        int k = i >> 4, c = i & 15;
        keyv[k * KP4 + c] = kg[k * 16 + c];
    }
    if (tid < 128) {
        int r = tid >> 4, c = tid & 15;
        reinterpret_cast<uint4*>(qw)[r * 16 + c] =
            reinterpret_cast<const uint4*>(q_h_g + (b * TOUT + q0 + r) * LH)[c];
        w3f[tid] = W3[tid];
    }
    __syncthreads();

    int ql = tid >> 5;            // warp-uniform q row
    int kk = tid & 31;            // chains kk, +32, +64, +96
    const uint4* qrow = reinterpret_cast<const uint4*>(qw) + ql * 16;

    float f0 = 0.f, f1 = 0.f, f2 = 0.f, f3 = 0.f;
    #pragma unroll
    for (int g = 0; g < 16; g++) {
        uint4 q4 = qrow[g];
        float4 wA = *reinterpret_cast<const float4*>(&w3f[g * 8]);
        float4 wB = *reinterpret_cast<const float4*>(&w3f[g * 8 + 4]);
        uint4 kA = keyv[kk * KP4 + g];
        uint4 kB = keyv[(kk + 32) * KP4 + g];
        uint4 kC = keyv[(kk + 64) * KP4 + g];
        uint4 kD = keyv[(kk + 96) * KP4 + g];
        SCORE2(kA.x, q4.x, wA.x, wA.y, f0);
        SCORE2(kB.x, q4.x, wA.x, wA.y, f1);
        SCORE2(kC.x, q4.x, wA.x, wA.y, f2);
        SCORE2(kD.x, q4.x, wA.x, wA.y, f3);
        SCORE2(kA.y, q4.y, wA.z, wA.w, f0);
        SCORE2(kB.y, q4.y, wA.z, wA.w, f1);
        SCORE2(kC.y, q4.y, wA.z, wA.w, f2);
        SCORE2(kD.y, q4.y, wA.z, wA.w, f3);
        SCORE2(kA.z, q4.z, wB.x, wB.y, f0);
        SCORE2(kB.z, q4.z, wB.x, wB.y, f1);
        SCORE2(kC.z, q4.z, wB.x, wB.y, f2);
        SCORE2(kD.z, q4.z, wB.x, wB.y, f3);
        SCORE2(kA.w, q4.w, wB.z, wB.w, f0);
        SCORE2(kB.w, q4.w, wB.z, wB.w, f1);
        SCORE2(kC.w, q4.w, wB.z, wB.w, f2);
        SCORE2(kD.w, q4.w, wB.z, wB.w, f3);
    }
    float* orow = sc_g + (b * TOUT + q0 + ql) * TIN + k0;
    orow[kk]      = f0;
    orow[kk + 32] = f1;
    orow[kk + 64] = f2;
    orow[kk + 96] = f3;
}

// ---------------------------------------------------------------------------
// K5: fused softmax + weighted (unchanged).
// ---------------------------------------------------------------------------
__global__ void __launch_bounds__(256) weighted_kernel(
    const float* __restrict__ sc_g, const float* __restrict__ att,
    float* __restrict__ out)
{
    int b  = blockIdx.y;
    int q0 = blockIdx.x * 16;
    int tid = threadIdx.x;

    __shared__ float a_s[16][TIN];
    for (int i = tid; i < 16 * TIN; i += 256) {
        int r = i >> 9, kk = i & 511;
        a_s[r][kk] = sc_g[(b * TOUT + q0 + r) * TIN + kk];
    }
    __syncthreads();

    int w = tid >> 5, lane = tid & 31;
    for (int r = w; r < 16; r += 8) {
        float* row = a_s[r];
        float v[16], mx = -1e30f;
        #pragma unroll
        for (int i = 0; i < 16; i++) {
            v[i] = row[lane + 32 * i];
            mx = fmaxf(mx, v[i]);
        }
        #pragma unroll
        for (int off = 16; off >= 1; off >>= 1)
            mx = fmaxf(mx, __shfl_xor_sync(0xffffffffu, mx, off));
        float s = 0.0f;
        #pragma unroll
        for (int i = 0; i < 16; i++) {
            v[i] = ex2f((v[i] - mx) * 1.442695041f);
            s += v[i];
        }
        #pragma unroll
        for (int off = 16; off >= 1; off >>= 1)
            s += __shfl_xor_sync(0xffffffffu, s, off);
        float inv = rcpf(s);
        #pragma unroll
        for (int i = 0; i < 16; i++)
            row[lane + 32 * i] = v[i] * inv;
    }
    __syncthreads();

    int d = tid & 127;
    int g = tid >> 7;
    float acc[8];
    #pragma unroll
    for (int i = 0; i < 8; i++) acc[i] = 0.0f;

    const float* ap = att + b * TIN * DATT + d;
    #pragma unroll 4
    for (int k = 0; k < TIN; k++) {
        float av = ap[k * DATT];
        #pragma unroll
        for (int i = 0; i < 8; i++)
            acc[i] += a_s[g * 8 + i][k] * av;
    }
    #pragma unroll
    for (int i = 0; i < 8; i++)
        out[(b * TOUT + q0 + g * 8 + i) * (LH + DATT) + LH + d] = acc[i];
}

// ---------------------------------------------------------------------------
extern "C" void kernel_launch(void* const* d_in, const int* in_sizes, int n_in,
                              void* d_out, int out_size)
{
    const float* inputs   = (const float*)d_in[0];
    const float* attended = (const float*)d_in[1];
    const float* Wk       = (const float*)d_in[2];
    const float* Wr       = (const float*)d_in[3];
    const float* lbias    = (const float*)d_in[4];
    const float* W1       = (const float*)d_in[5];
    const float* b1       = (const float*)d_in[6];
    const float* W2       = (const float*)d_in[7];
    const float* b2       = (const float*)d_in[8];
    const float* W3       = (const float*)d_in[9];
    float* out = (float*)d_out;

    cudaFuncSetAttribute(lstm_kernel,
                         cudaFuncAttributeMaxDynamicSharedMemorySize, LSTM_DSMEM);
    cudaFuncSetAttribute(score_kernel,
                         cudaFuncAttributeMaxDynamicSharedMemorySize, SCORE_DSMEM);

    proj_kernel<<<512, 128>>>(attended, W1, b1, g_keys_h,
                              inputs, Wk, lbias, g_xz);
    lstm_kernel<<<NB, 512, LSTM_DSMEM>>>(g_xz, Wr, out);
    q_kernel<<<NB * TOUT / 16, 128>>>(out, W2, b2, g_q_h);
    {
        dim3 grid(TIN / 128, TOUT / 8, NB);
        score_kernel<<<grid, 256, SCORE_DSMEM>>>(g_keys_h, g_q_h, W3, g_sc);
    }
    {
        dim3 grid(16, NB);
        weighted_kernel<<<grid, 256>>>(g_sc, attended, out);
    }
    (void)in_sizes; (void)n_in; (void)out_size;
}